// round 6
// baseline (speedup 1.0000x reference)
#include <cuda_runtime.h>
#include <math.h>
#include <float.h>

#define Nn   50000
#define Ee   800000
#define ET   (Nn + Ee)          // edges + self loops = 850000
#define SLOPE 0.2f
#define BETA  0.5f
#define CCONST 1.0f

// ------------------- scratch (device globals; no allocation) -------------------
__device__ float g_h1[(size_t)Nn * 256];   // layer1 projected features [N,4,64]
__device__ float g_x1[(size_t)Nn * 256];   // layer1 output after mix activation
__device__ float g_h2[(size_t)Nn * 64];    // layer2 projected features
__device__ float g_ssrc1[Nn * 4];
__device__ float g_sdst1[Nn * 4];
__device__ float g_ssrc2[Nn];
__device__ float g_sdst2[Nn];
__device__ int   g_deg[Nn];
__device__ int   g_cur[Nn];
__device__ int   g_off[Nn + 1];
__device__ int   g_csr[ET];                // src node id per CSR slot (grouped by dst)

// ------------------- helpers -------------------
__device__ __forceinline__ float lrelu(float v) { return v > 0.f ? v : SLOPE * v; }

__device__ __forceinline__ float wredmax(float v) {
#pragma unroll
    for (int o = 16; o; o >>= 1) v = fmaxf(v, __shfl_xor_sync(0xffffffffu, v, o));
    return v;
}
__device__ __forceinline__ float wredsum(float v) {
#pragma unroll
    for (int o = 16; o; o >>= 1) v += __shfl_xor_sync(0xffffffffu, v, o);
    return v;
}

// ------------------- GEMM: C[M,N] = A[M,K] @ B[K,N]; N%64==0, K%16==0 ---------
// 128x64 tile, 256 threads, 8x4 microtile.
__global__ __launch_bounds__(256) void sgemm(const float* __restrict__ A,
                                             const float* __restrict__ B,
                                             float* __restrict__ C,
                                             int M, int N, int K) {
    __shared__ float As[16][132];   // [k][m]
    __shared__ float Bs[16][64];    // [k][n]
    const int tid = threadIdx.x;
    const int tx = tid & 15;        // 16 column groups of 4
    const int ty = tid >> 4;        // 16 row groups of 8
    const int row0 = blockIdx.y * 128, col0 = blockIdx.x * 64;

    float acc[8][4];
#pragma unroll
    for (int i = 0; i < 8; i++)
#pragma unroll
        for (int j = 0; j < 4; j++) acc[i][j] = 0.f;

    for (int k0 = 0; k0 < K; k0 += 16) {
#pragma unroll
        for (int l = 0; l < 8; l++) {                 // A tile 128x16
            int idx = tid + l * 256;
            int kk = idx & 15, m = idx >> 4;
            int gm = row0 + m;
            As[kk][m] = (gm < M) ? A[(size_t)gm * K + k0 + kk] : 0.f;
        }
#pragma unroll
        for (int l = 0; l < 4; l++) {                 // B tile 16x64
            int idx = tid + l * 256;
            int kk = idx >> 6, n = idx & 63;
            Bs[kk][n] = B[(size_t)(k0 + kk) * N + col0 + n];
        }
        __syncthreads();
#pragma unroll
        for (int kk = 0; kk < 16; kk++) {
            float4 a0 = *(const float4*)&As[kk][ty * 8];
            float4 a1 = *(const float4*)&As[kk][ty * 8 + 4];
            float4 bv = *(const float4*)&Bs[kk][tx * 4];
            float av[8] = {a0.x, a0.y, a0.z, a0.w, a1.x, a1.y, a1.z, a1.w};
#pragma unroll
            for (int i = 0; i < 8; i++) {
                acc[i][0] += av[i] * bv.x;
                acc[i][1] += av[i] * bv.y;
                acc[i][2] += av[i] * bv.z;
                acc[i][3] += av[i] * bv.w;
            }
        }
        __syncthreads();
    }
#pragma unroll
    for (int i = 0; i < 8; i++) {
        int gm = row0 + ty * 8 + i;
        if (gm < M) {
            float4 v; v.x = acc[i][0]; v.y = acc[i][1]; v.z = acc[i][2]; v.w = acc[i][3];
            *(float4*)&C[(size_t)gm * N + col0 + tx * 4] = v;
        }
    }
}

// ------------------- CSR construction -------------------
__global__ void k_init_deg() {
    int i = blockIdx.x * blockDim.x + threadIdx.x;
    if (i < Nn) { g_deg[i] = 1; g_cur[i] = 0; }    // 1 = self loop
}
__global__ void k_count_edges(const int* __restrict__ ei) {
    int e = blockIdx.x * blockDim.x + threadIdx.x;
    if (e < Ee) atomicAdd(&g_deg[ei[Ee + e]], 1);
}
// Single-block 3-phase exclusive scan: thread-local sum -> shuffle block scan
// of 1024 thread totals -> sequential write-back (re-reads g_deg, L1-hot).
__global__ __launch_bounds__(1024) void k_scan_deg() {
    __shared__ int warpsum[32];
    const int t = threadIdx.x;
    const int lane = t & 31, wid = t >> 5;
    const int PER = (Nn + 1023) / 1024;          // 49
    const int base = t * PER;

    int sum = 0;
    for (int i = 0; i < PER; i++) {
        int idx = base + i;
        if (idx < Nn) sum += g_deg[idx];
    }
    // inclusive warp scan of thread totals
    int x = sum;
#pragma unroll
    for (int o = 1; o < 32; o <<= 1) {
        int y = __shfl_up_sync(0xffffffffu, x, o);
        if (lane >= o) x += y;
    }
    if (lane == 31) warpsum[wid] = x;
    __syncthreads();
    if (wid == 0) {
        int w = warpsum[lane];
#pragma unroll
        for (int o = 1; o < 32; o <<= 1) {
            int y = __shfl_up_sync(0xffffffffu, w, o);
            if (lane >= o) w += y;
        }
        warpsum[lane] = w;                        // inclusive scan of warp totals
    }
    __syncthreads();
    int run = (x - sum) + (wid ? warpsum[wid - 1] : 0);   // exclusive prefix for this thread
    for (int i = 0; i < PER; i++) {
        int idx = base + i;
        if (idx < Nn) { g_off[idx] = run; run += g_deg[idx]; }
    }
    if (t == 0) g_off[Nn] = warpsum[31];
}
__global__ void k_scatter_self() {
    int i = blockIdx.x * blockDim.x + threadIdx.x;
    if (i < Nn) {
        int p = atomicAdd(&g_cur[i], 1);
        g_csr[g_off[i] + p] = i;
    }
}
__global__ void k_scatter_edges(const int* __restrict__ ei) {
    int e = blockIdx.x * blockDim.x + threadIdx.x;
    if (e < Ee) {
        int d = ei[Ee + e];
        int p = atomicAdd(&g_cur[d], 1);
        g_csr[g_off[d] + p] = ei[e];
    }
}

// ------------------- attention scores -------------------
__global__ __launch_bounds__(256) void k_scores1(const float* __restrict__ a_src,
                                                 const float* __restrict__ a_dst) {
    int w = (blockIdx.x * blockDim.x + threadIdx.x) >> 5;
    if (w >= Nn) return;
    int lane = threadIdx.x & 31;
    const float* hrow = g_h1 + (size_t)w * 256;
#pragma unroll
    for (int h = 0; h < 4; h++) {
        float v0 = hrow[h * 64 + lane], v1 = hrow[h * 64 + lane + 32];
        float ps = v0 * a_src[h * 64 + lane] + v1 * a_src[h * 64 + lane + 32];
        float pd = v0 * a_dst[h * 64 + lane] + v1 * a_dst[h * 64 + lane + 32];
        ps = wredsum(ps); pd = wredsum(pd);
        if (lane == 0) { g_ssrc1[w * 4 + h] = ps; g_sdst1[w * 4 + h] = pd; }
    }
}
__global__ __launch_bounds__(256) void k_scores2(const float* __restrict__ a_src,
                                                 const float* __restrict__ a_dst) {
    int w = (blockIdx.x * blockDim.x + threadIdx.x) >> 5;
    if (w >= Nn) return;
    int lane = threadIdx.x & 31;
    const float* hrow = g_h2 + (size_t)w * 64;
    float v0 = hrow[lane], v1 = hrow[lane + 32];
    float ps = v0 * a_src[lane] + v1 * a_src[lane + 32];
    float pd = v0 * a_dst[lane] + v1 * a_dst[lane + 32];
    ps = wredsum(ps); pd = wredsum(pd);
    if (lane == 0) { g_ssrc2[w] = ps; g_sdst2[w] = pd; }
}

// ------------------- layer 1: softmax attention + aggregate + activation mix --
__global__ __launch_bounds__(256) void k_gat_agg1(const float* __restrict__ b1) {
    int w = (blockIdx.x * blockDim.x + threadIdx.x) >> 5;
    if (w >= Nn) return;
    const int lane = threadIdx.x & 31;
    const int beg = g_off[w], end = g_off[w + 1];

    const float sd0 = g_sdst1[w * 4 + 0];
    const float sd1 = g_sdst1[w * 4 + 1];
    const float sd2 = g_sdst1[w * 4 + 2];
    const float sd3 = g_sdst1[w * 4 + 3];

    // pass 1: per-head max over incoming edges
    float m0 = -FLT_MAX, m1 = -FLT_MAX, m2 = -FLT_MAX, m3 = -FLT_MAX;
    for (int j = beg + lane; j < end; j += 32) {
        int s = g_csr[j];
        float4 sv = *(const float4*)(g_ssrc1 + (size_t)s * 4);
        m0 = fmaxf(m0, lrelu(sv.x + sd0));
        m1 = fmaxf(m1, lrelu(sv.y + sd1));
        m2 = fmaxf(m2, lrelu(sv.z + sd2));
        m3 = fmaxf(m3, lrelu(sv.w + sd3));
    }
    m0 = wredmax(m0); m1 = wredmax(m1); m2 = wredmax(m2); m3 = wredmax(m3);

    // pass 2: per-head sum of exp
    float d0 = 0.f, d1 = 0.f, d2 = 0.f, d3 = 0.f;
    for (int j = beg + lane; j < end; j += 32) {
        int s = g_csr[j];
        float4 sv = *(const float4*)(g_ssrc1 + (size_t)s * 4);
        d0 += __expf(lrelu(sv.x + sd0) - m0);
        d1 += __expf(lrelu(sv.y + sd1) - m1);
        d2 += __expf(lrelu(sv.z + sd2) - m2);
        d3 += __expf(lrelu(sv.w + sd3) - m3);
    }
    d0 = wredsum(d0); d1 = wredsum(d1); d2 = wredsum(d2); d3 = wredsum(d3);
    const float i0 = 1.f / d0, i1 = 1.f / d1, i2 = 1.f / d2, i3 = 1.f / d3;

    // pass 3: accumulate features, 2 edges per iteration (MLP=2 on the 1KB rows).
    // lanes 0..7 compute softmax weights: lane = e*4+h (e in {0,1}, h in {0..3}).
    const int myh = lane >> 3;                 // head owned by this lane's feature slice
    const int hh = lane & 3;
    const float sdh = hh == 0 ? sd0 : hh == 1 ? sd1 : hh == 2 ? sd2 : sd3;
    const float mh  = hh == 0 ? m0  : hh == 1 ? m1  : hh == 2 ? m2  : m3;
    const float ih  = hh == 0 ? i0  : hh == 1 ? i1  : hh == 2 ? i2  : i3;

    float4 acc0 = make_float4(0.f, 0.f, 0.f, 0.f);
    float4 acc1 = make_float4(0.f, 0.f, 0.f, 0.f);
    int j = beg;
    for (; j + 1 < end; j += 2) {
        int s0 = g_csr[j], s1 = g_csr[j + 1];
        float wv = 0.f;
        if (lane < 8) {
            int ss = (lane < 4) ? s0 : s1;
            float e = lrelu(g_ssrc1[(size_t)ss * 4 + hh] + sdh);
            wv = __expf(e - mh) * ih;
        }
        float w0 = __shfl_sync(0xffffffffu, wv, myh);
        float w1 = __shfl_sync(0xffffffffu, wv, 4 + myh);
        const float4* hp0 = (const float4*)(g_h1 + (size_t)s0 * 256 + lane * 8);
        const float4* hp1 = (const float4*)(g_h1 + (size_t)s1 * 256 + lane * 8);
        float4 p0 = hp0[0], p1 = hp0[1];
        float4 q0 = hp1[0], q1 = hp1[1];
        acc0.x += w0 * p0.x + w1 * q0.x; acc0.y += w0 * p0.y + w1 * q0.y;
        acc0.z += w0 * p0.z + w1 * q0.z; acc0.w += w0 * p0.w + w1 * q0.w;
        acc1.x += w0 * p1.x + w1 * q1.x; acc1.y += w0 * p1.y + w1 * q1.y;
        acc1.z += w0 * p1.z + w1 * q1.z; acc1.w += w0 * p1.w + w1 * q1.w;
    }
    if (j < end) {                              // tail edge
        int s0 = g_csr[j];
        float wv = 0.f;
        if (lane < 4) {
            float e = lrelu(g_ssrc1[(size_t)s0 * 4 + hh] + sdh);
            wv = __expf(e - mh) * ih;
        }
        float w0 = __shfl_sync(0xffffffffu, wv, myh);
        const float4* hp0 = (const float4*)(g_h1 + (size_t)s0 * 256 + lane * 8);
        float4 p0 = hp0[0], p1 = hp0[1];
        acc0.x += w0 * p0.x; acc0.y += w0 * p0.y; acc0.z += w0 * p0.z; acc0.w += w0 * p0.w;
        acc1.x += w0 * p1.x; acc1.y += w0 * p1.y; acc1.z += w0 * p1.z; acc1.w += w0 * p1.w;
    }

    // z = agg + b1;  x1 = BETA*z + (C-BETA)*z*sigmoid(z)
    float zz[8] = {acc0.x, acc0.y, acc0.z, acc0.w, acc1.x, acc1.y, acc1.z, acc1.w};
    float out[8];
#pragma unroll
    for (int r = 0; r < 8; r++) {
        float z = zz[r] + b1[lane * 8 + r];
        float sg = 1.f / (1.f + __expf(-z));
        out[r] = BETA * z + (CCONST - BETA) * z * sg;
    }
    float* op = g_x1 + (size_t)w * 256 + lane * 8;
    *(float4*)op       = make_float4(out[0], out[1], out[2], out[3]);
    *(float4*)(op + 4) = make_float4(out[4], out[5], out[6], out[7]);
}

// ------------------- layer 2: softmax attention + aggregate (-> output) ------
__global__ __launch_bounds__(256) void k_gat_agg2(const float* __restrict__ b2,
                                                  float* __restrict__ outp) {
    int w = (blockIdx.x * blockDim.x + threadIdx.x) >> 5;
    if (w >= Nn) return;
    const int lane = threadIdx.x & 31;
    const int beg = g_off[w], end = g_off[w + 1];
    const float sd = g_sdst2[w];

    float m = -FLT_MAX;
    for (int j = beg + lane; j < end; j += 32)
        m = fmaxf(m, lrelu(g_ssrc2[g_csr[j]] + sd));
    m = wredmax(m);

    float ds = 0.f;
    for (int j = beg + lane; j < end; j += 32)
        ds += __expf(lrelu(g_ssrc2[g_csr[j]] + sd) - m);
    ds = wredsum(ds);
    const float inv = 1.f / ds;

    float2 acc = make_float2(0.f, 0.f);
    int j = beg;
    for (; j + 1 < end; j += 2) {
        int s0 = g_csr[j], s1 = g_csr[j + 1];
        float wv = 0.f;
        if (lane < 2) {
            int ss = (lane == 0) ? s0 : s1;
            wv = __expf(lrelu(g_ssrc2[ss] + sd) - m) * inv;
        }
        float w0 = __shfl_sync(0xffffffffu, wv, 0);
        float w1 = __shfl_sync(0xffffffffu, wv, 1);
        float2 v0 = ((const float2*)(g_h2 + (size_t)s0 * 64))[lane];
        float2 v1 = ((const float2*)(g_h2 + (size_t)s1 * 64))[lane];
        acc.x += w0 * v0.x + w1 * v1.x;
        acc.y += w0 * v0.y + w1 * v1.y;
    }
    if (j < end) {
        int s0 = g_csr[j];
        float wv = 0.f;
        if (lane == 0) wv = __expf(lrelu(g_ssrc2[s0] + sd) - m) * inv;
        float w0 = __shfl_sync(0xffffffffu, wv, 0);
        float2 v0 = ((const float2*)(g_h2 + (size_t)s0 * 64))[lane];
        acc.x += w0 * v0.x; acc.y += w0 * v0.y;
    }
    float2 r;
    r.x = CCONST * (acc.x + b2[lane * 2 + 0]);
    r.y = CCONST * (acc.y + b2[lane * 2 + 1]);
    ((float2*)(outp + (size_t)w * 64))[lane] = r;
}

// ------------------- launcher -------------------
extern "C" void kernel_launch(void* const* d_in, const int* in_sizes, int n_in,
                              void* d_out, int out_size) {
    const float* x      = (const float*)d_in[0];
    const int*   ei     = (const int*)d_in[1];
    const float* W1     = (const float*)d_in[2];
    const float* a_src1 = (const float*)d_in[3];
    const float* a_dst1 = (const float*)d_in[4];
    const float* b1     = (const float*)d_in[5];
    const float* W2     = (const float*)d_in[6];
    const float* a_src2 = (const float*)d_in[7];
    const float* a_dst2 = (const float*)d_in[8];
    const float* b2     = (const float*)d_in[9];
    float* outp = (float*)d_out;

    float *h1p, *x1p, *h2p;
    cudaGetSymbolAddress((void**)&h1p, g_h1);
    cudaGetSymbolAddress((void**)&x1p, g_x1);
    cudaGetSymbolAddress((void**)&h2p, g_h2);

    const int TB = 256;
    // CSR build
    k_init_deg<<<(Nn + TB - 1) / TB, TB>>>();
    k_count_edges<<<(Ee + TB - 1) / TB, TB>>>(ei);
    k_scan_deg<<<1, 1024>>>();
    k_scatter_self<<<(Nn + TB - 1) / TB, TB>>>();
    k_scatter_edges<<<(Ee + TB - 1) / TB, TB>>>(ei);

    // layer 1
    sgemm<<<dim3(256 / 64, (Nn + 127) / 128), 256>>>(x, W1, h1p, Nn, 256, 256);
    k_scores1<<<(Nn * 32) / TB, TB>>>(a_src1, a_dst1);
    k_gat_agg1<<<(Nn * 32) / TB, TB>>>(b1);

    // layer 2
    sgemm<<<dim3(64 / 64, (Nn + 127) / 128), 256>>>(x1p, W2, h2p, Nn, 64, 256);
    k_scores2<<<(Nn * 32) / TB, TB>>>(a_src2, a_dst2);
    k_gat_agg2<<<(Nn * 32) / TB, TB>>>(b2, outp);
}

// round 15
// speedup vs baseline: 1.0876x; 1.0876x over previous
#include <cuda_runtime.h>
#include <math.h>
#include <float.h>
#include <stdint.h>

#define Nn   50000
#define Ee   800000
#define ET   (Nn + Ee)          // edges + self loops = 850000
#define SLOPE 0.2f
#define BETA  0.5f
#define CCONST 1.0f

// ------------------- scratch (device globals; no allocation) -------------------
__device__ float g_h1[(size_t)Nn * 256];   // layer1 projected features [N,4,64]
__device__ float g_x1[(size_t)Nn * 256];   // layer1 output after mix activation
__device__ float g_h2[(size_t)Nn * 64];    // layer2 projected features
__device__ float g_ssrc1[Nn * 4];
__device__ float g_sdst1[Nn * 4];
__device__ float g_ssrc2[Nn];
__device__ float g_sdst2[Nn];
__device__ int   g_deg[Nn];
__device__ int   g_cur[Nn];
__device__ int   g_off[Nn + 1];
__device__ int   g_csr[ET];                // src node id per CSR slot (grouped by dst)

// ------------------- helpers -------------------
__device__ __forceinline__ float lrelu(float v) { return v > 0.f ? v : SLOPE * v; }

__device__ __forceinline__ float wredmax(float v) {
#pragma unroll
    for (int o = 16; o; o >>= 1) v = fmaxf(v, __shfl_xor_sync(0xffffffffu, v, o));
    return v;
}
__device__ __forceinline__ float wredsum(float v) {
#pragma unroll
    for (int o = 16; o; o >>= 1) v += __shfl_xor_sync(0xffffffffu, v, o);
    return v;
}

// tf32 hi/lo split for fp32-accuracy tensor GEMM (tf32x3 scheme, lo*lo dropped)
__device__ __forceinline__ void f2tf2(float a, uint32_t &hi, uint32_t &lo) {
    asm("cvt.rna.tf32.f32 %0, %1;" : "=r"(hi) : "f"(a));
    float r = a - __uint_as_float(hi);
    asm("cvt.rna.tf32.f32 %0, %1;" : "=r"(lo) : "f"(r));
}
__device__ __forceinline__ void mma8(float c[4], const uint32_t a[4], const uint32_t b[2]) {
    asm volatile("mma.sync.aligned.m16n8k8.row.col.f32.tf32.tf32.f32 "
                 "{%0,%1,%2,%3}, {%4,%5,%6,%7}, {%8,%9}, {%0,%1,%2,%3};"
                 : "+f"(c[0]), "+f"(c[1]), "+f"(c[2]), "+f"(c[3])
                 : "r"(a[0]), "r"(a[1]), "r"(a[2]), "r"(a[3]),
                   "r"(b[0]), "r"(b[1]));
}

// ------------------- tensor GEMM: C[M,N] = A[M,K] @ B[K,N] -------------------
// Requires N % 64 == 0, K % 32 == 0. Block 128x64, 8 warps (4m x 2n),
// warp tile 32x32 (2 x m16, 4 x n8), tf32x3 emulation (fp32 accuracy).
__global__ __launch_bounds__(256) void tgemm(const float* __restrict__ A,
                                             const float* __restrict__ B,
                                             float* __restrict__ C,
                                             int M, int N, int K) {
    __shared__ float As[128][36];   // pad 36: frag LDS bank = (4*row + k) % 32, conflict-free
    __shared__ float Bs[32][72];    // pad 72: frag LDS bank = (8*k + n) % 32, conflict-free
    const int tid  = threadIdx.x;
    const int warp = tid >> 5, lane = tid & 31;
    const int g = lane >> 2, t = lane & 3;      // group / thread-in-group
    const int wm = warp >> 1, wn = warp & 1;    // 4 x 2 warp grid
    const int row0 = blockIdx.y * 128, col0 = blockIdx.x * 64;

    float c[2][4][4];
#pragma unroll
    for (int ms = 0; ms < 2; ms++)
#pragma unroll
        for (int ns = 0; ns < 4; ns++)
#pragma unroll
            for (int r = 0; r < 4; r++) c[ms][ns][r] = 0.f;

    for (int k0 = 0; k0 < K; k0 += 32) {
        // A tile 128x32 (4 float4 per thread, coalesced: 8 threads per row)
#pragma unroll
        for (int i = 0; i < 4; i++) {
            int flat = (i * 256 + tid) * 4;
            int m = flat >> 5, kk = flat & 31;
            int gm = row0 + m;
            float4 v = (gm < M) ? *(const float4*)&A[(size_t)gm * K + k0 + kk]
                                : make_float4(0.f, 0.f, 0.f, 0.f);
            *(float4*)&As[m][kk] = v;
        }
        // B tile 32x64 (2 float4 per thread)
#pragma unroll
        for (int i = 0; i < 2; i++) {
            int flat = (i * 256 + tid) * 4;
            int kk = flat >> 6, n = flat & 63;
            *(float4*)&Bs[kk][n] = *(const float4*)&B[(size_t)(k0 + kk) * N + col0 + n];
        }
        __syncthreads();

#pragma unroll
        for (int ks = 0; ks < 32; ks += 8) {
            uint32_t ahi[2][4], alo[2][4];
#pragma unroll
            for (int ms = 0; ms < 2; ms++) {
                int rb = wm * 32 + ms * 16;
                f2tf2(As[rb + g][ks + t],         ahi[ms][0], alo[ms][0]);
                f2tf2(As[rb + 8 + g][ks + t],     ahi[ms][1], alo[ms][1]);
                f2tf2(As[rb + g][ks + t + 4],     ahi[ms][2], alo[ms][2]);
                f2tf2(As[rb + 8 + g][ks + t + 4], ahi[ms][3], alo[ms][3]);
            }
            uint32_t bhi[4][2], blo[4][2];
#pragma unroll
            for (int ns = 0; ns < 4; ns++) {
                int cb = wn * 32 + ns * 8 + g;
                f2tf2(Bs[ks + t][cb],     bhi[ns][0], blo[ns][0]);
                f2tf2(Bs[ks + t + 4][cb], bhi[ns][1], blo[ns][1]);
            }
#pragma unroll
            for (int ms = 0; ms < 2; ms++)
#pragma unroll
                for (int ns = 0; ns < 4; ns++) {
                    mma8(c[ms][ns], ahi[ms], bhi[ns]);   // hi*hi
                    mma8(c[ms][ns], ahi[ms], blo[ns]);   // hi*lo
                    mma8(c[ms][ns], alo[ms], bhi[ns]);   // lo*hi
                }
        }
        __syncthreads();
    }

    // epilogue: c0 -> (r, 2t), c1 -> (r, 2t+1), c2 -> (r+8, 2t), c3 -> (r+8, 2t+1)
#pragma unroll
    for (int ms = 0; ms < 2; ms++)
#pragma unroll
        for (int ns = 0; ns < 4; ns++) {
            int r  = row0 + wm * 32 + ms * 16 + g;
            int cc = col0 + wn * 32 + ns * 8 + 2 * t;
            if (r < M)
                *(float2*)&C[(size_t)r * N + cc]       = make_float2(c[ms][ns][0], c[ms][ns][1]);
            if (r + 8 < M)
                *(float2*)&C[(size_t)(r + 8) * N + cc] = make_float2(c[ms][ns][2], c[ms][ns][3]);
        }
}

// ------------------- CSR construction -------------------
__global__ void k_init_deg() {
    int i = blockIdx.x * blockDim.x + threadIdx.x;
    if (i < Nn) { g_deg[i] = 1; g_cur[i] = 0; }    // 1 = self loop
}
__global__ void k_count_edges(const int* __restrict__ ei) {
    int e = blockIdx.x * blockDim.x + threadIdx.x;
    if (e < Ee) atomicAdd(&g_deg[ei[Ee + e]], 1);
}
// Single-block 3-phase exclusive scan.
__global__ __launch_bounds__(1024) void k_scan_deg() {
    __shared__ int warpsum[32];
    const int t = threadIdx.x;
    const int lane = t & 31, wid = t >> 5;
    const int PER = (Nn + 1023) / 1024;          // 49
    const int base = t * PER;

    int sum = 0;
    for (int i = 0; i < PER; i++) {
        int idx = base + i;
        if (idx < Nn) sum += g_deg[idx];
    }
    int x = sum;
#pragma unroll
    for (int o = 1; o < 32; o <<= 1) {
        int y = __shfl_up_sync(0xffffffffu, x, o);
        if (lane >= o) x += y;
    }
    if (lane == 31) warpsum[wid] = x;
    __syncthreads();
    if (wid == 0) {
        int w = warpsum[lane];
#pragma unroll
        for (int o = 1; o < 32; o <<= 1) {
            int y = __shfl_up_sync(0xffffffffu, w, o);
            if (lane >= o) w += y;
        }
        warpsum[lane] = w;
    }
    __syncthreads();
    int run = (x - sum) + (wid ? warpsum[wid - 1] : 0);
    for (int i = 0; i < PER; i++) {
        int idx = base + i;
        if (idx < Nn) { g_off[idx] = run; run += g_deg[idx]; }
    }
    if (t == 0) g_off[Nn] = warpsum[31];
}
__global__ void k_scatter_self() {
    int i = blockIdx.x * blockDim.x + threadIdx.x;
    if (i < Nn) {
        int p = atomicAdd(&g_cur[i], 1);
        g_csr[g_off[i] + p] = i;
    }
}
__global__ void k_scatter_edges(const int* __restrict__ ei) {
    int e = blockIdx.x * blockDim.x + threadIdx.x;
    if (e < Ee) {
        int d = ei[Ee + e];
        int p = atomicAdd(&g_cur[d], 1);
        g_csr[g_off[d] + p] = ei[e];
    }
}

// ------------------- attention scores -------------------
__global__ __launch_bounds__(256) void k_scores1(const float* __restrict__ a_src,
                                                 const float* __restrict__ a_dst) {
    int w = (blockIdx.x * blockDim.x + threadIdx.x) >> 5;
    if (w >= Nn) return;
    int lane = threadIdx.x & 31;
    const float* hrow = g_h1 + (size_t)w * 256;
#pragma unroll
    for (int h = 0; h < 4; h++) {
        float v0 = hrow[h * 64 + lane], v1 = hrow[h * 64 + lane + 32];
        float ps = v0 * a_src[h * 64 + lane] + v1 * a_src[h * 64 + lane + 32];
        float pd = v0 * a_dst[h * 64 + lane] + v1 * a_dst[h * 64 + lane + 32];
        ps = wredsum(ps); pd = wredsum(pd);
        if (lane == 0) { g_ssrc1[w * 4 + h] = ps; g_sdst1[w * 4 + h] = pd; }
    }
}
__global__ __launch_bounds__(256) void k_scores2(const float* __restrict__ a_src,
                                                 const float* __restrict__ a_dst) {
    int w = (blockIdx.x * blockDim.x + threadIdx.x) >> 5;
    if (w >= Nn) return;
    int lane = threadIdx.x & 31;
    const float* hrow = g_h2 + (size_t)w * 64;
    float v0 = hrow[lane], v1 = hrow[lane + 32];
    float ps = v0 * a_src[lane] + v1 * a_src[lane + 32];
    float pd = v0 * a_dst[lane] + v1 * a_dst[lane + 32];
    ps = wredsum(ps); pd = wredsum(pd);
    if (lane == 0) { g_ssrc2[w] = ps; g_sdst2[w] = pd; }
}

// ------------------- layer 1: softmax attention + aggregate + activation mix --
__global__ __launch_bounds__(256) void k_gat_agg1(const float* __restrict__ b1) {
    int w = (blockIdx.x * blockDim.x + threadIdx.x) >> 5;
    if (w >= Nn) return;
    const int lane = threadIdx.x & 31;
    const int beg = g_off[w], end = g_off[w + 1];

    const float sd0 = g_sdst1[w * 4 + 0];
    const float sd1 = g_sdst1[w * 4 + 1];
    const float sd2 = g_sdst1[w * 4 + 2];
    const float sd3 = g_sdst1[w * 4 + 3];

    float m0 = -FLT_MAX, m1 = -FLT_MAX, m2 = -FLT_MAX, m3 = -FLT_MAX;
    for (int j = beg + lane; j < end; j += 32) {
        int s = g_csr[j];
        float4 sv = *(const float4*)(g_ssrc1 + (size_t)s * 4);
        m0 = fmaxf(m0, lrelu(sv.x + sd0));
        m1 = fmaxf(m1, lrelu(sv.y + sd1));
        m2 = fmaxf(m2, lrelu(sv.z + sd2));
        m3 = fmaxf(m3, lrelu(sv.w + sd3));
    }
    m0 = wredmax(m0); m1 = wredmax(m1); m2 = wredmax(m2); m3 = wredmax(m3);

    float d0 = 0.f, d1 = 0.f, d2 = 0.f, d3 = 0.f;
    for (int j = beg + lane; j < end; j += 32) {
        int s = g_csr[j];
        float4 sv = *(const float4*)(g_ssrc1 + (size_t)s * 4);
        d0 += __expf(lrelu(sv.x + sd0) - m0);
        d1 += __expf(lrelu(sv.y + sd1) - m1);
        d2 += __expf(lrelu(sv.z + sd2) - m2);
        d3 += __expf(lrelu(sv.w + sd3) - m3);
    }
    d0 = wredsum(d0); d1 = wredsum(d1); d2 = wredsum(d2); d3 = wredsum(d3);
    const float i0 = 1.f / d0, i1 = 1.f / d1, i2 = 1.f / d2, i3 = 1.f / d3;

    const int myh = lane >> 3;
    const int hh = lane & 3;
    const float sdh = hh == 0 ? sd0 : hh == 1 ? sd1 : hh == 2 ? sd2 : sd3;
    const float mh  = hh == 0 ? m0  : hh == 1 ? m1  : hh == 2 ? m2  : m3;
    const float ih  = hh == 0 ? i0  : hh == 1 ? i1  : hh == 2 ? i2  : i3;

    float4 acc0 = make_float4(0.f, 0.f, 0.f, 0.f);
    float4 acc1 = make_float4(0.f, 0.f, 0.f, 0.f);
    int j = beg;
    for (; j + 1 < end; j += 2) {
        int s0 = g_csr[j], s1 = g_csr[j + 1];
        float wv = 0.f;
        if (lane < 8) {
            int ss = (lane < 4) ? s0 : s1;
            float e = lrelu(g_ssrc1[(size_t)ss * 4 + hh] + sdh);
            wv = __expf(e - mh) * ih;
        }
        float w0 = __shfl_sync(0xffffffffu, wv, myh);
        float w1 = __shfl_sync(0xffffffffu, wv, 4 + myh);
        const float4* hp0 = (const float4*)(g_h1 + (size_t)s0 * 256 + lane * 8);
        const float4* hp1 = (const float4*)(g_h1 + (size_t)s1 * 256 + lane * 8);
        float4 p0 = hp0[0], p1 = hp0[1];
        float4 q0 = hp1[0], q1 = hp1[1];
        acc0.x += w0 * p0.x + w1 * q0.x; acc0.y += w0 * p0.y + w1 * q0.y;
        acc0.z += w0 * p0.z + w1 * q0.z; acc0.w += w0 * p0.w + w1 * q0.w;
        acc1.x += w0 * p1.x + w1 * q1.x; acc1.y += w0 * p1.y + w1 * q1.y;
        acc1.z += w0 * p1.z + w1 * q1.z; acc1.w += w0 * p1.w + w1 * q1.w;
    }
    if (j < end) {
        int s0 = g_csr[j];
        float wv = 0.f;
        if (lane < 4) {
            float e = lrelu(g_ssrc1[(size_t)s0 * 4 + hh] + sdh);
            wv = __expf(e - mh) * ih;
        }
        float w0 = __shfl_sync(0xffffffffu, wv, myh);
        const float4* hp0 = (const float4*)(g_h1 + (size_t)s0 * 256 + lane * 8);
        float4 p0 = hp0[0], p1 = hp0[1];
        acc0.x += w0 * p0.x; acc0.y += w0 * p0.y; acc0.z += w0 * p0.z; acc0.w += w0 * p0.w;
        acc1.x += w0 * p1.x; acc1.y += w0 * p1.y; acc1.z += w0 * p1.z; acc1.w += w0 * p1.w;
    }

    float zz[8] = {acc0.x, acc0.y, acc0.z, acc0.w, acc1.x, acc1.y, acc1.z, acc1.w};
    float out[8];
#pragma unroll
    for (int r = 0; r < 8; r++) {
        float z = zz[r] + b1[lane * 8 + r];
        float sg = 1.f / (1.f + __expf(-z));
        out[r] = BETA * z + (CCONST - BETA) * z * sg;
    }
    float* op = g_x1 + (size_t)w * 256 + lane * 8;
    *(float4*)op       = make_float4(out[0], out[1], out[2], out[3]);
    *(float4*)(op + 4) = make_float4(out[4], out[5], out[6], out[7]);
}

// ------------------- layer 2: softmax attention + aggregate (-> output) ------
__global__ __launch_bounds__(256) void k_gat_agg2(const float* __restrict__ b2,
                                                  float* __restrict__ outp) {
    int w = (blockIdx.x * blockDim.x + threadIdx.x) >> 5;
    if (w >= Nn) return;
    const int lane = threadIdx.x & 31;
    const int beg = g_off[w], end = g_off[w + 1];
    const float sd = g_sdst2[w];

    float m = -FLT_MAX;
    for (int j = beg + lane; j < end; j += 32)
        m = fmaxf(m, lrelu(g_ssrc2[g_csr[j]] + sd));
    m = wredmax(m);

    float ds = 0.f;
    for (int j = beg + lane; j < end; j += 32)
        ds += __expf(lrelu(g_ssrc2[g_csr[j]] + sd) - m);
    ds = wredsum(ds);
    const float inv = 1.f / ds;

    float2 acc = make_float2(0.f, 0.f);
    int j = beg;
    for (; j + 1 < end; j += 2) {
        int s0 = g_csr[j], s1 = g_csr[j + 1];
        float wv = 0.f;
        if (lane < 2) {
            int ss = (lane == 0) ? s0 : s1;
            wv = __expf(lrelu(g_ssrc2[ss] + sd) - m) * inv;
        }
        float w0 = __shfl_sync(0xffffffffu, wv, 0);
        float w1 = __shfl_sync(0xffffffffu, wv, 1);
        float2 v0 = ((const float2*)(g_h2 + (size_t)s0 * 64))[lane];
        float2 v1 = ((const float2*)(g_h2 + (size_t)s1 * 64))[lane];
        acc.x += w0 * v0.x + w1 * v1.x;
        acc.y += w0 * v0.y + w1 * v1.y;
    }
    if (j < end) {
        int s0 = g_csr[j];
        float wv = 0.f;
        if (lane == 0) wv = __expf(lrelu(g_ssrc2[s0] + sd) - m) * inv;
        float w0 = __shfl_sync(0xffffffffu, wv, 0);
        float2 v0 = ((const float2*)(g_h2 + (size_t)s0 * 64))[lane];
        acc.x += w0 * v0.x; acc.y += w0 * v0.y;
    }
    float2 r;
    r.x = CCONST * (acc.x + b2[lane * 2 + 0]);
    r.y = CCONST * (acc.y + b2[lane * 2 + 1]);
    ((float2*)(outp + (size_t)w * 64))[lane] = r;
}

// ------------------- launcher -------------------
extern "C" void kernel_launch(void* const* d_in, const int* in_sizes, int n_in,
                              void* d_out, int out_size) {
    const float* x      = (const float*)d_in[0];
    const int*   ei     = (const int*)d_in[1];
    const float* W1     = (const float*)d_in[2];
    const float* a_src1 = (const float*)d_in[3];
    const float* a_dst1 = (const float*)d_in[4];
    const float* b1     = (const float*)d_in[5];
    const float* W2     = (const float*)d_in[6];
    const float* a_src2 = (const float*)d_in[7];
    const float* a_dst2 = (const float*)d_in[8];
    const float* b2     = (const float*)d_in[9];
    float* outp = (float*)d_out;

    float *h1p, *x1p, *h2p;
    cudaGetSymbolAddress((void**)&h1p, g_h1);
    cudaGetSymbolAddress((void**)&x1p, g_x1);
    cudaGetSymbolAddress((void**)&h2p, g_h2);

    const int TB = 256;
    // CSR build
    k_init_deg<<<(Nn + TB - 1) / TB, TB>>>();
    k_count_edges<<<(Ee + TB - 1) / TB, TB>>>(ei);
    k_scan_deg<<<1, 1024>>>();
    k_scatter_self<<<(Nn + TB - 1) / TB, TB>>>();
    k_scatter_edges<<<(Ee + TB - 1) / TB, TB>>>(ei);

    // layer 1
    tgemm<<<dim3(256 / 64, (Nn + 127) / 128), 256>>>(x, W1, h1p, Nn, 256, 256);
    k_scores1<<<(Nn * 32) / TB, TB>>>(a_src1, a_dst1);
    k_gat_agg1<<<(Nn * 32) / TB, TB>>>(b1);

    // layer 2
    tgemm<<<dim3(64 / 64, (Nn + 127) / 128), 256>>>(x1p, W2, h2p, Nn, 64, 256);
    k_scores2<<<(Nn * 32) / TB, TB>>>(a_src2, a_dst2);
    k_gat_agg2<<<(Nn * 32) / TB, TB>>>(b2, outp);
}